// round 4
// baseline (speedup 1.0000x reference)
#include <cuda_runtime.h>
#include <math.h>

#define BATCH 64
#define SEQ   512
#define EMB   512
#define HID   1024

#define NCTA      128           // recurrence grid (<=148 -> all co-resident)
#define W_STRIDE  1028          // 1024 + 4 pad (bank-conflict break), float4-aligned
#define A_STRIDE  68            // 64 + 4 pad, float4-aligned
#define ABUF      (32 * A_STRIDE)
#define RNN_SMEM_FLOATS (16 * W_STRIDE + 2 * ABUF)
#define RNN_SMEM_BYTES  (RNN_SMEM_FLOATS * 4)

// ---------------- device scratch (static: no runtime allocation) ----------------
__device__ float    g_a[2][BATCH * HID];   // recurrent state, double buffered
__device__ unsigned g_bar;                 // grid barrier counter

// ---------------- kernel 0: per-launch init (graph replays must be deterministic) ----
__global__ void init_kernel() {
    int idx = blockIdx.x * blockDim.x + threadIdx.x;
    if (idx < BATCH * HID) g_a[0][idx] = 0.0f;
    if (idx == 0) g_bar = 0u;
}

// ---------------- kernel 1: xproj GEMM ----------------
// out[(s*64+b)*1024 + h] = sum_e X[b][s][e] * W_ax[h][e] + b_a[h]
// 128x128 tile, k-chunk 8, 256 threads, 8x8 microtile
__global__ __launch_bounds__(256, 2)
void xproj_kernel(const float* __restrict__ X, const float* __restrict__ Wax,
                  const float* __restrict__ ba, float* __restrict__ out)
{
    __shared__ float As[8][128];
    __shared__ float Bs[8][128];

    const int bm = blockIdx.y;          // 0..255
    const int bn = blockIdx.x;          // 0..7
    const int t  = threadIdx.x;
    const int tx = t & 15;
    const int ty = t >> 4;

    const int lrow = t >> 1;            // 0..127
    const int lkq  = (t & 1) * 4;       // 0 or 4

    // A row (m = s*64 + b): contiguous in e
    const int m  = bm * 128 + lrow;
    const int sA = m >> 6;
    const int bA = m & 63;
    const float* Arow = X + ((size_t)bA * SEQ + sA) * EMB;
    const float* Brow = Wax + (size_t)(bn * 128 + lrow) * EMB;

    float acc[8][8];
#pragma unroll
    for (int i = 0; i < 8; i++)
#pragma unroll
        for (int j = 0; j < 8; j++) acc[i][j] = 0.0f;

    for (int k0 = 0; k0 < EMB; k0 += 8) {
        float4 av = *(const float4*)(Arow + k0 + lkq);
        float4 bv = *(const float4*)(Brow + k0 + lkq);
        __syncthreads();
        As[lkq + 0][lrow] = av.x; As[lkq + 1][lrow] = av.y;
        As[lkq + 2][lrow] = av.z; As[lkq + 3][lrow] = av.w;
        Bs[lkq + 0][lrow] = bv.x; Bs[lkq + 1][lrow] = bv.y;
        Bs[lkq + 2][lrow] = bv.z; Bs[lkq + 3][lrow] = bv.w;
        __syncthreads();
#pragma unroll
        for (int k = 0; k < 8; k++) {
            float a_f[8], b_f[8];
            *(float4*)&a_f[0] = *(const float4*)&As[k][ty * 8];
            *(float4*)&a_f[4] = *(const float4*)&As[k][ty * 8 + 4];
            *(float4*)&b_f[0] = *(const float4*)&Bs[k][tx * 8];
            *(float4*)&b_f[4] = *(const float4*)&Bs[k][tx * 8 + 4];
#pragma unroll
            for (int i = 0; i < 8; i++)
#pragma unroll
                for (int j = 0; j < 8; j++)
                    acc[i][j] += a_f[i] * b_f[j];
        }
    }

    const int n0 = bn * 128 + tx * 8;
    const int m0 = bm * 128 + ty * 8;
    float4 bl = *(const float4*)(ba + n0);
    float4 bh = *(const float4*)(ba + n0 + 4);
#pragma unroll
    for (int i = 0; i < 8; i++) {
        size_t ro = (size_t)(m0 + i) * HID + n0;
        float4 o0 = make_float4(acc[i][0] + bl.x, acc[i][1] + bl.y,
                                acc[i][2] + bl.z, acc[i][3] + bl.w);
        float4 o1 = make_float4(acc[i][4] + bh.x, acc[i][5] + bh.y,
                                acc[i][6] + bh.z, acc[i][7] + bh.w);
        *(float4*)(out + ro)     = o0;
        *(float4*)(out + ro + 4) = o1;
    }
}

// ---------------- kernel 2: persistent recurrence ----------------
// 128 CTAs, 128 threads. CTA tile: 32 b x 16 h, W rows pinned in SMEM.
// out holds xproj on entry; overwritten in place with tanh outputs.
__global__ __launch_bounds__(128, 1)
void rnn_kernel(const float* __restrict__ Waa, float* __restrict__ out,
                float* __restrict__ hid)
{
    extern __shared__ float smem[];
    float* Wsm = smem;                      // 16 x W_STRIDE
    float* Asm = smem + 16 * W_STRIDE;      // 2 x 32 x A_STRIDE

    const int t   = threadIdx.x;
    const int cta = blockIdx.x;             // 0..127
    const int hg  = cta >> 1;               // 0..63
    const int bg  = cta & 1;                // 0..1
    const int h0  = hg * 16;
    const int b0  = bg * 32;

    const int th = t & 7;                   // h-pair select (0..7)
    const int tb = t >> 3;                  // b-pair select (0..15)
    const int hA = h0 + 2 * th;
    const int bA = b0 + 2 * tb;

    // pin this CTA's 16 W_aa rows in SMEM (once, reused for all 512 steps)
    for (int idx = t; idx < 16 * 256; idx += 128) {
        int r = idx >> 8, c4 = idx & 255;
        float4 v = *(const float4*)(Waa + (size_t)(h0 + r) * HID + c4 * 4);
        *(float4*)&Wsm[r * W_STRIDE + c4 * 4] = v;
    }
    __syncthreads();

    unsigned target = gridDim.x;

#pragma unroll 1
    for (int s = 0; s < SEQ; s++) {
        const float* acur = g_a[s & 1];
        float*       anxt = g_a[(s + 1) & 1];

        float acc00 = 0.f, acc01 = 0.f, acc10 = 0.f, acc11 = 0.f;

        // prologue: stage a-chunk 0 (32 b x 64 k)
        float4 pre[4];
#pragma unroll
        for (int j = 0; j < 4; j++) {
            int f = t + 128 * j, r = f >> 4, c4 = f & 15;
            pre[j] = *(const float4*)(acur + (size_t)(b0 + r) * HID + c4 * 4);
        }
#pragma unroll
        for (int j = 0; j < 4; j++) {
            int f = t + 128 * j, r = f >> 4, c4 = f & 15;
            *(float4*)&Asm[r * A_STRIDE + c4 * 4] = pre[j];
        }
        __syncthreads();

#pragma unroll 1
        for (int c = 0; c < 16; c++) {
            const int cb = c & 1;
            if (c < 15) {
                const int k0n = (c + 1) * 64;
#pragma unroll
                for (int j = 0; j < 4; j++) {
                    int f = t + 128 * j, r = f >> 4, c4 = f & 15;
                    pre[j] = *(const float4*)(acur + (size_t)(b0 + r) * HID + k0n + c4 * 4);
                }
            }
            const float* A0 = Asm + cb * ABUF + (2 * tb) * A_STRIDE;
            const float* A1 = A0 + A_STRIDE;
            const float* W0 = Wsm + (2 * th) * W_STRIDE + c * 64;
            const float* W1 = W0 + W_STRIDE;
#pragma unroll
            for (int kk = 0; kk < 16; kk++) {
                float4 a0 = *(const float4*)(A0 + kk * 4);
                float4 a1 = *(const float4*)(A1 + kk * 4);
                float4 w0 = *(const float4*)(W0 + kk * 4);
                float4 w1 = *(const float4*)(W1 + kk * 4);
                acc00 += a0.x * w0.x; acc00 += a0.y * w0.y;
                acc00 += a0.z * w0.z; acc00 += a0.w * w0.w;
                acc01 += a0.x * w1.x; acc01 += a0.y * w1.y;
                acc01 += a0.z * w1.z; acc01 += a0.w * w1.w;
                acc10 += a1.x * w0.x; acc10 += a1.y * w0.y;
                acc10 += a1.z * w0.z; acc10 += a1.w * w0.w;
                acc11 += a1.x * w1.x; acc11 += a1.y * w1.y;
                acc11 += a1.z * w1.z; acc11 += a1.w * w1.w;
            }
            if (c < 15) {
#pragma unroll
                for (int j = 0; j < 4; j++) {
                    int f = t + 128 * j, r = f >> 4, c4 = f & 15;
                    *(float4*)&Asm[(cb ^ 1) * ABUF + r * A_STRIDE + c4 * 4] = pre[j];
                }
            }
            __syncthreads();
        }

        // epilogue: tanh(acc + xproj), write outputs (in place) + next state
        {
            const size_t base = (size_t)s * (BATCH * HID);
            const int i00 = bA * HID + hA;
            float2 xp0 = *(const float2*)(out + base + i00);
            float2 xp1 = *(const float2*)(out + base + i00 + HID);
            float2 r0 = make_float2(tanhf(acc00 + xp0.x), tanhf(acc01 + xp0.y));
            float2 r1 = make_float2(tanhf(acc10 + xp1.x), tanhf(acc11 + xp1.y));
            *(float2*)(out + base + i00)       = r0;
            *(float2*)(out + base + i00 + HID) = r1;
            *(float2*)(anxt + i00)             = r0;
            *(float2*)(anxt + i00 + HID)       = r1;
            if (hid && s == SEQ - 1) {
                *(float2*)(hid + i00)       = r0;
                *(float2*)(hid + i00 + HID) = r1;
            }
        }

        // grid barrier (release/acquire through L2) — all 128 CTAs co-resident
        __threadfence();
        __syncthreads();
        if (t == 0) {
            asm volatile("red.release.gpu.add.u32 [%0], 1;" :: "l"(&g_bar) : "memory");
            unsigned v;
            do {
                asm volatile("ld.acquire.gpu.u32 %0, [%1];" : "=r"(v) : "l"(&g_bar) : "memory");
            } while (v < target);
        }
        __syncthreads();
        target += gridDim.x;
    }
}

// ---------------- host launcher ----------------
extern "C" void kernel_launch(void* const* d_in, const int* in_sizes, int n_in,
                              void* d_out, int out_size)
{
    // map inputs by element count (robust to ordering)
    const float *X = nullptr, *Wax = nullptr, *Waa = nullptr, *ba = nullptr;
    for (int i = 0; i < n_in; i++) {
        switch (in_sizes[i]) {
            case BATCH * SEQ * EMB: X   = (const float*)d_in[i]; break;
            case HID * EMB:         Wax = (const float*)d_in[i]; break;
            case HID * HID:         Waa = (const float*)d_in[i]; break;
            case HID:               ba  = (const float*)d_in[i]; break;
            default: break;
        }
    }
    if (!X || !Wax || !Waa || !ba) {       // fallback: positional
        X   = (const float*)d_in[0];
        Wax = (const float*)d_in[1];
        Waa = (const float*)d_in[2];
        ba  = (const float*)d_in[3];
    }

    const long long needOut = (long long)SEQ * BATCH * HID;           // outputs
    if ((long long)out_size < needOut) return;                        // unexpected layout
    float* outp = (float*)d_out;
    float* hidp = ((long long)out_size >= needOut + (long long)BATCH * HID)
                      ? outp + needOut : nullptr;

    cudaFuncSetAttribute(rnn_kernel, cudaFuncAttributeMaxDynamicSharedMemorySize,
                         RNN_SMEM_BYTES);

    init_kernel<<<256, 256>>>();
    xproj_kernel<<<dim3(8, 256), 256>>>(X, Wax, ba, outp);
    rnn_kernel<<<NCTA, 128, RNN_SMEM_BYTES>>>(Waa, outp, hidp);
}

// round 5
// speedup vs baseline: 1.0015x; 1.0015x over previous
#include <cuda_runtime.h>
#include <math.h>

#define BATCH 64
#define SEQ   512
#define EMB   512
#define HID   1024

#define NCTA      128           // recurrence grid (<=148 -> all co-resident)
#define W_STRIDE  1028          // 1024 + 4 pad (bank-conflict break), float4-aligned
#define A_STRIDE  68            // 64 + 4 pad, float4-aligned
#define ABUF      (32 * A_STRIDE)
#define RNN_SMEM_FLOATS (16 * W_STRIDE + 2 * ABUF)
#define RNN_SMEM_BYTES  (RNN_SMEM_FLOATS * 4)

// ---------------- device scratch (static: no runtime allocation) ----------------
__device__ float    g_a[2][BATCH * HID];   // recurrent state, double buffered
__device__ unsigned g_bar;                 // grid barrier counter

// ---------------- kernel 0: per-launch init (graph replays must be deterministic) ----
__global__ void init_kernel() {
    int idx = blockIdx.x * blockDim.x + threadIdx.x;
    if (idx < BATCH * HID) g_a[0][idx] = 0.0f;
    if (idx == 0) g_bar = 0u;
}

// ---------------- kernel 1: xproj GEMM ----------------
// out[(s*64+b)*1024 + h] = sum_e X[b][s][e] * W_ax[h][e] + b_a[h]
// 128x128 tile, k-chunk 8, 256 threads, 8x8 microtile
__global__ __launch_bounds__(256, 2)
void xproj_kernel(const float* __restrict__ X, const float* __restrict__ Wax,
                  const float* __restrict__ ba, float* __restrict__ out)
{
    __shared__ float As[8][128];
    __shared__ float Bs[8][128];

    const int bm = blockIdx.y;          // 0..255
    const int bn = blockIdx.x;          // 0..7
    const int t  = threadIdx.x;
    const int tx = t & 15;
    const int ty = t >> 4;

    const int lrow = t >> 1;            // 0..127
    const int lkq  = (t & 1) * 4;       // 0 or 4

    // A row (m = s*64 + b): contiguous in e
    const int m  = bm * 128 + lrow;
    const int sA = m >> 6;
    const int bA = m & 63;
    const float* Arow = X + ((size_t)bA * SEQ + sA) * EMB;
    const float* Brow = Wax + (size_t)(bn * 128 + lrow) * EMB;

    float acc[8][8];
#pragma unroll
    for (int i = 0; i < 8; i++)
#pragma unroll
        for (int j = 0; j < 8; j++) acc[i][j] = 0.0f;

    for (int k0 = 0; k0 < EMB; k0 += 8) {
        float4 av = *(const float4*)(Arow + k0 + lkq);
        float4 bv = *(const float4*)(Brow + k0 + lkq);
        __syncthreads();
        As[lkq + 0][lrow] = av.x; As[lkq + 1][lrow] = av.y;
        As[lkq + 2][lrow] = av.z; As[lkq + 3][lrow] = av.w;
        Bs[lkq + 0][lrow] = bv.x; Bs[lkq + 1][lrow] = bv.y;
        Bs[lkq + 2][lrow] = bv.z; Bs[lkq + 3][lrow] = bv.w;
        __syncthreads();
#pragma unroll
        for (int k = 0; k < 8; k++) {
            float a_f[8], b_f[8];
            *(float4*)&a_f[0] = *(const float4*)&As[k][ty * 8];
            *(float4*)&a_f[4] = *(const float4*)&As[k][ty * 8 + 4];
            *(float4*)&b_f[0] = *(const float4*)&Bs[k][tx * 8];
            *(float4*)&b_f[4] = *(const float4*)&Bs[k][tx * 8 + 4];
#pragma unroll
            for (int i = 0; i < 8; i++)
#pragma unroll
                for (int j = 0; j < 8; j++)
                    acc[i][j] += a_f[i] * b_f[j];
        }
    }

    const int n0 = bn * 128 + tx * 8;
    const int m0 = bm * 128 + ty * 8;
    float4 bl = *(const float4*)(ba + n0);
    float4 bh = *(const float4*)(ba + n0 + 4);
#pragma unroll
    for (int i = 0; i < 8; i++) {
        size_t ro = (size_t)(m0 + i) * HID + n0;
        float4 o0 = make_float4(acc[i][0] + bl.x, acc[i][1] + bl.y,
                                acc[i][2] + bl.z, acc[i][3] + bl.w);
        float4 o1 = make_float4(acc[i][4] + bh.x, acc[i][5] + bh.y,
                                acc[i][6] + bh.z, acc[i][7] + bh.w);
        *(float4*)(out + ro)     = o0;
        *(float4*)(out + ro + 4) = o1;
    }
}

// ---------------- kernel 2: persistent recurrence ----------------
// 128 CTAs, 128 threads. CTA tile: 32 b x 16 h, W rows pinned in SMEM.
// out holds xproj on entry; overwritten in place with tanh outputs.
__global__ __launch_bounds__(128, 1)
void rnn_kernel(const float* __restrict__ Waa, float* __restrict__ out,
                float* __restrict__ hid)
{
    extern __shared__ float smem[];
    float* Wsm = smem;                      // 16 x W_STRIDE
    float* Asm = smem + 16 * W_STRIDE;      // 2 x 32 x A_STRIDE

    const int t   = threadIdx.x;
    const int cta = blockIdx.x;             // 0..127
    const int hg  = cta >> 1;               // 0..63
    const int bg  = cta & 1;                // 0..1
    const int h0  = hg * 16;
    const int b0  = bg * 32;

    const int th = t & 7;                   // h-pair select (0..7)
    const int tb = t >> 3;                  // b-pair select (0..15)
    const int hA = h0 + 2 * th;
    const int bA = b0 + 2 * tb;

    // pin this CTA's 16 W_aa rows in SMEM (once, reused for all 512 steps)
    for (int idx = t; idx < 16 * 256; idx += 128) {
        int r = idx >> 8, c4 = idx & 255;
        float4 v = *(const float4*)(Waa + (size_t)(h0 + r) * HID + c4 * 4);
        *(float4*)&Wsm[r * W_STRIDE + c4 * 4] = v;
    }
    __syncthreads();

    unsigned target = gridDim.x;

#pragma unroll 1
    for (int s = 0; s < SEQ; s++) {
        const float* acur = g_a[s & 1];
        float*       anxt = g_a[(s + 1) & 1];

        float acc00 = 0.f, acc01 = 0.f, acc10 = 0.f, acc11 = 0.f;

        // prologue: stage a-chunk 0 (32 b x 64 k)
        float4 pre[4];
#pragma unroll
        for (int j = 0; j < 4; j++) {
            int f = t + 128 * j, r = f >> 4, c4 = f & 15;
            pre[j] = *(const float4*)(acur + (size_t)(b0 + r) * HID + c4 * 4);
        }
#pragma unroll
        for (int j = 0; j < 4; j++) {
            int f = t + 128 * j, r = f >> 4, c4 = f & 15;
            *(float4*)&Asm[r * A_STRIDE + c4 * 4] = pre[j];
        }
        __syncthreads();

#pragma unroll 1
        for (int c = 0; c < 16; c++) {
            const int cb = c & 1;
            if (c < 15) {
                const int k0n = (c + 1) * 64;
#pragma unroll
                for (int j = 0; j < 4; j++) {
                    int f = t + 128 * j, r = f >> 4, c4 = f & 15;
                    pre[j] = *(const float4*)(acur + (size_t)(b0 + r) * HID + k0n + c4 * 4);
                }
            }
            const float* A0 = Asm + cb * ABUF + (2 * tb) * A_STRIDE;
            const float* A1 = A0 + A_STRIDE;
            const float* W0 = Wsm + (2 * th) * W_STRIDE + c * 64;
            const float* W1 = W0 + W_STRIDE;
#pragma unroll
            for (int kk = 0; kk < 16; kk++) {
                float4 a0 = *(const float4*)(A0 + kk * 4);
                float4 a1 = *(const float4*)(A1 + kk * 4);
                float4 w0 = *(const float4*)(W0 + kk * 4);
                float4 w1 = *(const float4*)(W1 + kk * 4);
                acc00 += a0.x * w0.x; acc00 += a0.y * w0.y;
                acc00 += a0.z * w0.z; acc00 += a0.w * w0.w;
                acc01 += a0.x * w1.x; acc01 += a0.y * w1.y;
                acc01 += a0.z * w1.z; acc01 += a0.w * w1.w;
                acc10 += a1.x * w0.x; acc10 += a1.y * w0.y;
                acc10 += a1.z * w0.z; acc10 += a1.w * w0.w;
                acc11 += a1.x * w1.x; acc11 += a1.y * w1.y;
                acc11 += a1.z * w1.z; acc11 += a1.w * w1.w;
            }
            if (c < 15) {
#pragma unroll
                for (int j = 0; j < 4; j++) {
                    int f = t + 128 * j, r = f >> 4, c4 = f & 15;
                    *(float4*)&Asm[(cb ^ 1) * ABUF + r * A_STRIDE + c4 * 4] = pre[j];
                }
            }
            __syncthreads();
        }

        // epilogue: tanh(acc + xproj), write outputs (in place) + next state
        {
            const size_t base = (size_t)s * (BATCH * HID);
            const int i00 = bA * HID + hA;
            float2 xp0 = *(const float2*)(out + base + i00);
            float2 xp1 = *(const float2*)(out + base + i00 + HID);
            float2 r0 = make_float2(tanhf(acc00 + xp0.x), tanhf(acc01 + xp0.y));
            float2 r1 = make_float2(tanhf(acc10 + xp1.x), tanhf(acc11 + xp1.y));
            *(float2*)(out + base + i00)       = r0;
            *(float2*)(out + base + i00 + HID) = r1;
            *(float2*)(anxt + i00)             = r0;
            *(float2*)(anxt + i00 + HID)       = r1;
            if (hid && s == SEQ - 1) {
                *(float2*)(hid + i00)       = r0;
                *(float2*)(hid + i00 + HID) = r1;
            }
        }

        // grid barrier (release/acquire through L2) — all 128 CTAs co-resident
        __threadfence();
        __syncthreads();
        if (t == 0) {
            asm volatile("red.release.gpu.add.u32 [%0], 1;" :: "l"(&g_bar) : "memory");
            unsigned v;
            do {
                asm volatile("ld.acquire.gpu.u32 %0, [%1];" : "=r"(v) : "l"(&g_bar) : "memory");
            } while (v < target);
        }
        __syncthreads();
        target += gridDim.x;
    }
}

// ---------------- host launcher ----------------
extern "C" void kernel_launch(void* const* d_in, const int* in_sizes, int n_in,
                              void* d_out, int out_size)
{
    // map inputs by element count (robust to ordering)
    const float *X = nullptr, *Wax = nullptr, *Waa = nullptr, *ba = nullptr;
    for (int i = 0; i < n_in; i++) {
        switch (in_sizes[i]) {
            case BATCH * SEQ * EMB: X   = (const float*)d_in[i]; break;
            case HID * EMB:         Wax = (const float*)d_in[i]; break;
            case HID * HID:         Waa = (const float*)d_in[i]; break;
            case HID:               ba  = (const float*)d_in[i]; break;
            default: break;
        }
    }
    if (!X || !Wax || !Waa || !ba) {       // fallback: positional
        X   = (const float*)d_in[0];
        Wax = (const float*)d_in[1];
        Waa = (const float*)d_in[2];
        ba  = (const float*)d_in[3];
    }

    const long long needOut = (long long)SEQ * BATCH * HID;           // outputs
    if ((long long)out_size < needOut) return;                        // unexpected layout
    float* outp = (float*)d_out;
    float* hidp = ((long long)out_size >= needOut + (long long)BATCH * HID)
                      ? outp + needOut : nullptr;

    cudaFuncSetAttribute(rnn_kernel, cudaFuncAttributeMaxDynamicSharedMemorySize,
                         RNN_SMEM_BYTES);

    init_kernel<<<256, 256>>>();
    xproj_kernel<<<dim3(8, 256), 256>>>(X, Wax, ba, outp);
    rnn_kernel<<<NCTA, 128, RNN_SMEM_BYTES>>>(Waa, outp, hidp);
}

// round 8
// speedup vs baseline: 1.0028x; 1.0013x over previous
#include <cuda_runtime.h>
#include <math.h>

#define BATCH 64
#define SEQ   512
#define EMB   512
#define HID   1024

#define NCTA      128           // recurrence grid (<=148 -> all co-resident)
#define W_STRIDE  1028          // 1024 + 4 pad (bank-conflict break), float4-aligned
#define A_STRIDE  68            // 64 + 4 pad, float4-aligned
#define ABUF      (32 * A_STRIDE)
#define RNN_SMEM_FLOATS (16 * W_STRIDE + 2 * ABUF)
#define RNN_SMEM_BYTES  (RNN_SMEM_FLOATS * 4)

// ---------------- device scratch (static: no runtime allocation) ----------------
__device__ float    g_a[2][BATCH * HID];   // recurrent state, double buffered
__device__ unsigned g_bar;                 // grid barrier counter

// ---------------- kernel 0: per-launch init (graph replays must be deterministic) ----
__global__ void init_kernel() {
    int idx = blockIdx.x * blockDim.x + threadIdx.x;
    if (idx < BATCH * HID) g_a[0][idx] = 0.0f;
    if (idx == 0) g_bar = 0u;
}

// ---------------- kernel 1: xproj GEMM ----------------
// out[(s*64+b)*1024 + h] = sum_e X[b][s][e] * W_ax[h][e] + b_a[h]
// 128x128 tile, k-chunk 8, 256 threads, 8x8 microtile
__global__ __launch_bounds__(256, 2)
void xproj_kernel(const float* __restrict__ X, const float* __restrict__ Wax,
                  const float* __restrict__ ba, float* __restrict__ out)
{
    __shared__ float As[8][128];
    __shared__ float Bs[8][128];

    const int bm = blockIdx.y;          // 0..255
    const int bn = blockIdx.x;          // 0..7
    const int t  = threadIdx.x;
    const int tx = t & 15;
    const int ty = t >> 4;

    const int lrow = t >> 1;            // 0..127
    const int lkq  = (t & 1) * 4;       // 0 or 4

    // A row (m = s*64 + b): contiguous in e
    const int m  = bm * 128 + lrow;
    const int sA = m >> 6;
    const int bA = m & 63;
    const float* Arow = X + ((size_t)bA * SEQ + sA) * EMB;
    const float* Brow = Wax + (size_t)(bn * 128 + lrow) * EMB;

    float acc[8][8];
#pragma unroll
    for (int i = 0; i < 8; i++)
#pragma unroll
        for (int j = 0; j < 8; j++) acc[i][j] = 0.0f;

    for (int k0 = 0; k0 < EMB; k0 += 8) {
        float4 av = *(const float4*)(Arow + k0 + lkq);
        float4 bv = *(const float4*)(Brow + k0 + lkq);
        __syncthreads();
        As[lkq + 0][lrow] = av.x; As[lkq + 1][lrow] = av.y;
        As[lkq + 2][lrow] = av.z; As[lkq + 3][lrow] = av.w;
        Bs[lkq + 0][lrow] = bv.x; Bs[lkq + 1][lrow] = bv.y;
        Bs[lkq + 2][lrow] = bv.z; Bs[lkq + 3][lrow] = bv.w;
        __syncthreads();
#pragma unroll
        for (int k = 0; k < 8; k++) {
            float a_f[8], b_f[8];
            *(float4*)&a_f[0] = *(const float4*)&As[k][ty * 8];
            *(float4*)&a_f[4] = *(const float4*)&As[k][ty * 8 + 4];
            *(float4*)&b_f[0] = *(const float4*)&Bs[k][tx * 8];
            *(float4*)&b_f[4] = *(const float4*)&Bs[k][tx * 8 + 4];
#pragma unroll
            for (int i = 0; i < 8; i++)
#pragma unroll
                for (int j = 0; j < 8; j++)
                    acc[i][j] += a_f[i] * b_f[j];
        }
    }

    const int n0 = bn * 128 + tx * 8;
    const int m0 = bm * 128 + ty * 8;
    float4 bl = *(const float4*)(ba + n0);
    float4 bh = *(const float4*)(ba + n0 + 4);
#pragma unroll
    for (int i = 0; i < 8; i++) {
        size_t ro = (size_t)(m0 + i) * HID + n0;
        float4 o0 = make_float4(acc[i][0] + bl.x, acc[i][1] + bl.y,
                                acc[i][2] + bl.z, acc[i][3] + bl.w);
        float4 o1 = make_float4(acc[i][4] + bh.x, acc[i][5] + bh.y,
                                acc[i][6] + bh.z, acc[i][7] + bh.w);
        *(float4*)(out + ro)     = o0;
        *(float4*)(out + ro + 4) = o1;
    }
}

// ---------------- kernel 2: persistent recurrence ----------------
// 128 CTAs, 128 threads. CTA tile: 32 b x 16 h, W rows pinned in SMEM.
// out holds xproj on entry; overwritten in place with tanh outputs.
__global__ __launch_bounds__(128, 1)
void rnn_kernel(const float* __restrict__ Waa, float* __restrict__ out,
                float* __restrict__ hid)
{
    extern __shared__ float smem[];
    float* Wsm = smem;                      // 16 x W_STRIDE
    float* Asm = smem + 16 * W_STRIDE;      // 2 x 32 x A_STRIDE

    const int t   = threadIdx.x;
    const int cta = blockIdx.x;             // 0..127
    const int hg  = cta >> 1;               // 0..63
    const int bg  = cta & 1;                // 0..1
    const int h0  = hg * 16;
    const int b0  = bg * 32;

    const int th = t & 7;                   // h-pair select (0..7)
    const int tb = t >> 3;                  // b-pair select (0..15)
    const int hA = h0 + 2 * th;
    const int bA = b0 + 2 * tb;

    // pin this CTA's 16 W_aa rows in SMEM (once, reused for all 512 steps)
    for (int idx = t; idx < 16 * 256; idx += 128) {
        int r = idx >> 8, c4 = idx & 255;
        float4 v = *(const float4*)(Waa + (size_t)(h0 + r) * HID + c4 * 4);
        *(float4*)&Wsm[r * W_STRIDE + c4 * 4] = v;
    }
    __syncthreads();

    unsigned target = gridDim.x;

#pragma unroll 1
    for (int s = 0; s < SEQ; s++) {
        const float* acur = g_a[s & 1];
        float*       anxt = g_a[(s + 1) & 1];

        float acc00 = 0.f, acc01 = 0.f, acc10 = 0.f, acc11 = 0.f;

        // prologue: stage a-chunk 0 (32 b x 64 k)
        float4 pre[4];
#pragma unroll
        for (int j = 0; j < 4; j++) {
            int f = t + 128 * j, r = f >> 4, c4 = f & 15;
            pre[j] = *(const float4*)(acur + (size_t)(b0 + r) * HID + c4 * 4);
        }
#pragma unroll
        for (int j = 0; j < 4; j++) {
            int f = t + 128 * j, r = f >> 4, c4 = f & 15;
            *(float4*)&Asm[r * A_STRIDE + c4 * 4] = pre[j];
        }
        __syncthreads();

#pragma unroll 1
        for (int c = 0; c < 16; c++) {
            const int cb = c & 1;
            if (c < 15) {
                const int k0n = (c + 1) * 64;
#pragma unroll
                for (int j = 0; j < 4; j++) {
                    int f = t + 128 * j, r = f >> 4, c4 = f & 15;
                    pre[j] = *(const float4*)(acur + (size_t)(b0 + r) * HID + k0n + c4 * 4);
                }
            }
            const float* A0 = Asm + cb * ABUF + (2 * tb) * A_STRIDE;
            const float* A1 = A0 + A_STRIDE;
            const float* W0 = Wsm + (2 * th) * W_STRIDE + c * 64;
            const float* W1 = W0 + W_STRIDE;
#pragma unroll
            for (int kk = 0; kk < 16; kk++) {
                float4 a0 = *(const float4*)(A0 + kk * 4);
                float4 a1 = *(const float4*)(A1 + kk * 4);
                float4 w0 = *(const float4*)(W0 + kk * 4);
                float4 w1 = *(const float4*)(W1 + kk * 4);
                acc00 += a0.x * w0.x; acc00 += a0.y * w0.y;
                acc00 += a0.z * w0.z; acc00 += a0.w * w0.w;
                acc01 += a0.x * w1.x; acc01 += a0.y * w1.y;
                acc01 += a0.z * w1.z; acc01 += a0.w * w1.w;
                acc10 += a1.x * w0.x; acc10 += a1.y * w0.y;
                acc10 += a1.z * w0.z; acc10 += a1.w * w0.w;
                acc11 += a1.x * w1.x; acc11 += a1.y * w1.y;
                acc11 += a1.z * w1.z; acc11 += a1.w * w1.w;
            }
            if (c < 15) {
#pragma unroll
                for (int j = 0; j < 4; j++) {
                    int f = t + 128 * j, r = f >> 4, c4 = f & 15;
                    *(float4*)&Asm[(cb ^ 1) * ABUF + r * A_STRIDE + c4 * 4] = pre[j];
                }
            }
            __syncthreads();
        }

        // epilogue: tanh(acc + xproj), write outputs (in place) + next state
        {
            const size_t base = (size_t)s * (BATCH * HID);
            const int i00 = bA * HID + hA;
            float2 xp0 = *(const float2*)(out + base + i00);
            float2 xp1 = *(const float2*)(out + base + i00 + HID);
            float2 r0 = make_float2(tanhf(acc00 + xp0.x), tanhf(acc01 + xp0.y));
            float2 r1 = make_float2(tanhf(acc10 + xp1.x), tanhf(acc11 + xp1.y));
            *(float2*)(out + base + i00)       = r0;
            *(float2*)(out + base + i00 + HID) = r1;
            *(float2*)(anxt + i00)             = r0;
            *(float2*)(anxt + i00 + HID)       = r1;
            if (hid && s == SEQ - 1) {
                *(float2*)(hid + i00)       = r0;
                *(float2*)(hid + i00 + HID) = r1;
            }
        }

        // grid barrier (release/acquire through L2) — all 128 CTAs co-resident
        __threadfence();
        __syncthreads();
        if (t == 0) {
            asm volatile("red.release.gpu.add.u32 [%0], 1;" :: "l"(&g_bar) : "memory");
            unsigned v;
            do {
                asm volatile("ld.acquire.gpu.u32 %0, [%1];" : "=r"(v) : "l"(&g_bar) : "memory");
            } while (v < target);
        }
        __syncthreads();
        target += gridDim.x;
    }
}

// ---------------- host launcher ----------------
extern "C" void kernel_launch(void* const* d_in, const int* in_sizes, int n_in,
                              void* d_out, int out_size)
{
    // map inputs by element count (robust to ordering)
    const float *X = nullptr, *Wax = nullptr, *Waa = nullptr, *ba = nullptr;
    for (int i = 0; i < n_in; i++) {
        switch (in_sizes[i]) {
            case BATCH * SEQ * EMB: X   = (const float*)d_in[i]; break;
            case HID * EMB:         Wax = (const float*)d_in[i]; break;
            case HID * HID:         Waa = (const float*)d_in[i]; break;
            case HID:               ba  = (const float*)d_in[i]; break;
            default: break;
        }
    }
    if (!X || !Wax || !Waa || !ba) {       // fallback: positional
        X   = (const float*)d_in[0];
        Wax = (const float*)d_in[1];
        Waa = (const float*)d_in[2];
        ba  = (const float*)d_in[3];
    }

    const long long needOut = (long long)SEQ * BATCH * HID;           // outputs
    if ((long long)out_size < needOut) return;                        // unexpected layout
    float* outp = (float*)d_out;
    float* hidp = ((long long)out_size >= needOut + (long long)BATCH * HID)
                      ? outp + needOut : nullptr;

    cudaFuncSetAttribute(rnn_kernel, cudaFuncAttributeMaxDynamicSharedMemorySize,
                         RNN_SMEM_BYTES);

    init_kernel<<<256, 256>>>();
    xproj_kernel<<<dim3(8, 256), 256>>>(X, Wax, ba, outp);
    rnn_kernel<<<NCTA, 128, RNN_SMEM_BYTES>>>(Waa, outp, hidp);
}

// round 9
// speedup vs baseline: 1.0032x; 1.0003x over previous
#include <cuda_runtime.h>
#include <math.h>

#define BATCH 64
#define SEQ   512
#define EMB   512
#define HID   1024

#define NCTA      128           // recurrence grid (<=148 -> all co-resident)
#define W_STRIDE  1028          // 1024 + 4 pad (bank-conflict break), float4-aligned
#define A_STRIDE  68            // 64 + 4 pad, float4-aligned
#define ABUF      (32 * A_STRIDE)
#define RNN_SMEM_FLOATS (16 * W_STRIDE + 2 * ABUF)
#define RNN_SMEM_BYTES  (RNN_SMEM_FLOATS * 4)

// ---------------- device scratch (static: no runtime allocation) ----------------
__device__ float    g_a[2][BATCH * HID];   // recurrent state, double buffered
__device__ unsigned g_bar;                 // grid barrier counter

// ---------------- kernel 0: per-launch init (graph replays must be deterministic) ----
__global__ void init_kernel() {
    int idx = blockIdx.x * blockDim.x + threadIdx.x;
    if (idx < BATCH * HID) g_a[0][idx] = 0.0f;
    if (idx == 0) g_bar = 0u;
}

// ---------------- kernel 1: xproj GEMM ----------------
// out[(s*64+b)*1024 + h] = sum_e X[b][s][e] * W_ax[h][e] + b_a[h]
// 128x128 tile, k-chunk 8, 256 threads, 8x8 microtile
__global__ __launch_bounds__(256, 2)
void xproj_kernel(const float* __restrict__ X, const float* __restrict__ Wax,
                  const float* __restrict__ ba, float* __restrict__ out)
{
    __shared__ float As[8][128];
    __shared__ float Bs[8][128];

    const int bm = blockIdx.y;          // 0..255
    const int bn = blockIdx.x;          // 0..7
    const int t  = threadIdx.x;
    const int tx = t & 15;
    const int ty = t >> 4;

    const int lrow = t >> 1;            // 0..127
    const int lkq  = (t & 1) * 4;       // 0 or 4

    // A row (m = s*64 + b): contiguous in e
    const int m  = bm * 128 + lrow;
    const int sA = m >> 6;
    const int bA = m & 63;
    const float* Arow = X + ((size_t)bA * SEQ + sA) * EMB;
    const float* Brow = Wax + (size_t)(bn * 128 + lrow) * EMB;

    float acc[8][8];
#pragma unroll
    for (int i = 0; i < 8; i++)
#pragma unroll
        for (int j = 0; j < 8; j++) acc[i][j] = 0.0f;

    for (int k0 = 0; k0 < EMB; k0 += 8) {
        float4 av = *(const float4*)(Arow + k0 + lkq);
        float4 bv = *(const float4*)(Brow + k0 + lkq);
        __syncthreads();
        As[lkq + 0][lrow] = av.x; As[lkq + 1][lrow] = av.y;
        As[lkq + 2][lrow] = av.z; As[lkq + 3][lrow] = av.w;
        Bs[lkq + 0][lrow] = bv.x; Bs[lkq + 1][lrow] = bv.y;
        Bs[lkq + 2][lrow] = bv.z; Bs[lkq + 3][lrow] = bv.w;
        __syncthreads();
#pragma unroll
        for (int k = 0; k < 8; k++) {
            float a_f[8], b_f[8];
            *(float4*)&a_f[0] = *(const float4*)&As[k][ty * 8];
            *(float4*)&a_f[4] = *(const float4*)&As[k][ty * 8 + 4];
            *(float4*)&b_f[0] = *(const float4*)&Bs[k][tx * 8];
            *(float4*)&b_f[4] = *(const float4*)&Bs[k][tx * 8 + 4];
#pragma unroll
            for (int i = 0; i < 8; i++)
#pragma unroll
                for (int j = 0; j < 8; j++)
                    acc[i][j] += a_f[i] * b_f[j];
        }
    }

    const int n0 = bn * 128 + tx * 8;
    const int m0 = bm * 128 + ty * 8;
    float4 bl = *(const float4*)(ba + n0);
    float4 bh = *(const float4*)(ba + n0 + 4);
#pragma unroll
    for (int i = 0; i < 8; i++) {
        size_t ro = (size_t)(m0 + i) * HID + n0;
        float4 o0 = make_float4(acc[i][0] + bl.x, acc[i][1] + bl.y,
                                acc[i][2] + bl.z, acc[i][3] + bl.w);
        float4 o1 = make_float4(acc[i][4] + bh.x, acc[i][5] + bh.y,
                                acc[i][6] + bh.z, acc[i][7] + bh.w);
        *(float4*)(out + ro)     = o0;
        *(float4*)(out + ro + 4) = o1;
    }
}

// ---------------- kernel 2: persistent recurrence ----------------
// 128 CTAs, 128 threads. CTA tile: 32 b x 16 h, W rows pinned in SMEM.
// out holds xproj on entry; overwritten in place with tanh outputs.
__global__ __launch_bounds__(128, 1)
void rnn_kernel(const float* __restrict__ Waa, float* __restrict__ out,
                float* __restrict__ hid)
{
    extern __shared__ float smem[];
    float* Wsm = smem;                      // 16 x W_STRIDE
    float* Asm = smem + 16 * W_STRIDE;      // 2 x 32 x A_STRIDE

    const int t   = threadIdx.x;
    const int cta = blockIdx.x;             // 0..127
    const int hg  = cta >> 1;               // 0..63
    const int bg  = cta & 1;                // 0..1
    const int h0  = hg * 16;
    const int b0  = bg * 32;

    const int th = t & 7;                   // h-pair select (0..7)
    const int tb = t >> 3;                  // b-pair select (0..15)
    const int hA = h0 + 2 * th;
    const int bA = b0 + 2 * tb;

    // pin this CTA's 16 W_aa rows in SMEM (once, reused for all 512 steps)
    for (int idx = t; idx < 16 * 256; idx += 128) {
        int r = idx >> 8, c4 = idx & 255;
        float4 v = *(const float4*)(Waa + (size_t)(h0 + r) * HID + c4 * 4);
        *(float4*)&Wsm[r * W_STRIDE + c4 * 4] = v;
    }
    __syncthreads();

    unsigned target = gridDim.x;

#pragma unroll 1
    for (int s = 0; s < SEQ; s++) {
        const float* acur = g_a[s & 1];
        float*       anxt = g_a[(s + 1) & 1];

        float acc00 = 0.f, acc01 = 0.f, acc10 = 0.f, acc11 = 0.f;

        // prologue: stage a-chunk 0 (32 b x 64 k)
        float4 pre[4];
#pragma unroll
        for (int j = 0; j < 4; j++) {
            int f = t + 128 * j, r = f >> 4, c4 = f & 15;
            pre[j] = *(const float4*)(acur + (size_t)(b0 + r) * HID + c4 * 4);
        }
#pragma unroll
        for (int j = 0; j < 4; j++) {
            int f = t + 128 * j, r = f >> 4, c4 = f & 15;
            *(float4*)&Asm[r * A_STRIDE + c4 * 4] = pre[j];
        }
        __syncthreads();

#pragma unroll 1
        for (int c = 0; c < 16; c++) {
            const int cb = c & 1;
            if (c < 15) {
                const int k0n = (c + 1) * 64;
#pragma unroll
                for (int j = 0; j < 4; j++) {
                    int f = t + 128 * j, r = f >> 4, c4 = f & 15;
                    pre[j] = *(const float4*)(acur + (size_t)(b0 + r) * HID + k0n + c4 * 4);
                }
            }
            const float* A0 = Asm + cb * ABUF + (2 * tb) * A_STRIDE;
            const float* A1 = A0 + A_STRIDE;
            const float* W0 = Wsm + (2 * th) * W_STRIDE + c * 64;
            const float* W1 = W0 + W_STRIDE;
#pragma unroll
            for (int kk = 0; kk < 16; kk++) {
                float4 a0 = *(const float4*)(A0 + kk * 4);
                float4 a1 = *(const float4*)(A1 + kk * 4);
                float4 w0 = *(const float4*)(W0 + kk * 4);
                float4 w1 = *(const float4*)(W1 + kk * 4);
                acc00 += a0.x * w0.x; acc00 += a0.y * w0.y;
                acc00 += a0.z * w0.z; acc00 += a0.w * w0.w;
                acc01 += a0.x * w1.x; acc01 += a0.y * w1.y;
                acc01 += a0.z * w1.z; acc01 += a0.w * w1.w;
                acc10 += a1.x * w0.x; acc10 += a1.y * w0.y;
                acc10 += a1.z * w0.z; acc10 += a1.w * w0.w;
                acc11 += a1.x * w1.x; acc11 += a1.y * w1.y;
                acc11 += a1.z * w1.z; acc11 += a1.w * w1.w;
            }
            if (c < 15) {
#pragma unroll
                for (int j = 0; j < 4; j++) {
                    int f = t + 128 * j, r = f >> 4, c4 = f & 15;
                    *(float4*)&Asm[(cb ^ 1) * ABUF + r * A_STRIDE + c4 * 4] = pre[j];
                }
            }
            __syncthreads();
        }

        // epilogue: tanh(acc + xproj), write outputs (in place) + next state
        {
            const size_t base = (size_t)s * (BATCH * HID);
            const int i00 = bA * HID + hA;
            float2 xp0 = *(const float2*)(out + base + i00);
            float2 xp1 = *(const float2*)(out + base + i00 + HID);
            float2 r0 = make_float2(tanhf(acc00 + xp0.x), tanhf(acc01 + xp0.y));
            float2 r1 = make_float2(tanhf(acc10 + xp1.x), tanhf(acc11 + xp1.y));
            *(float2*)(out + base + i00)       = r0;
            *(float2*)(out + base + i00 + HID) = r1;
            *(float2*)(anxt + i00)             = r0;
            *(float2*)(anxt + i00 + HID)       = r1;
            if (hid && s == SEQ - 1) {
                *(float2*)(hid + i00)       = r0;
                *(float2*)(hid + i00 + HID) = r1;
            }
        }

        // grid barrier (release/acquire through L2) — all 128 CTAs co-resident
        __threadfence();
        __syncthreads();
        if (t == 0) {
            asm volatile("red.release.gpu.add.u32 [%0], 1;" :: "l"(&g_bar) : "memory");
            unsigned v;
            do {
                asm volatile("ld.acquire.gpu.u32 %0, [%1];" : "=r"(v) : "l"(&g_bar) : "memory");
            } while (v < target);
        }
        __syncthreads();
        target += gridDim.x;
    }
}

// ---------------- host launcher ----------------
extern "C" void kernel_launch(void* const* d_in, const int* in_sizes, int n_in,
                              void* d_out, int out_size)
{
    // map inputs by element count (robust to ordering)
    const float *X = nullptr, *Wax = nullptr, *Waa = nullptr, *ba = nullptr;
    for (int i = 0; i < n_in; i++) {
        switch (in_sizes[i]) {
            case BATCH * SEQ * EMB: X   = (const float*)d_in[i]; break;
            case HID * EMB:         Wax = (const float*)d_in[i]; break;
            case HID * HID:         Waa = (const float*)d_in[i]; break;
            case HID:               ba  = (const float*)d_in[i]; break;
            default: break;
        }
    }
    if (!X || !Wax || !Waa || !ba) {       // fallback: positional
        X   = (const float*)d_in[0];
        Wax = (const float*)d_in[1];
        Waa = (const float*)d_in[2];
        ba  = (const float*)d_in[3];
    }

    const long long needOut = (long long)SEQ * BATCH * HID;           // outputs
    if ((long long)out_size < needOut) return;                        // unexpected layout
    float* outp = (float*)d_out;
    float* hidp = ((long long)out_size >= needOut + (long long)BATCH * HID)
                      ? outp + needOut : nullptr;

    cudaFuncSetAttribute(rnn_kernel, cudaFuncAttributeMaxDynamicSharedMemorySize,
                         RNN_SMEM_BYTES);

    init_kernel<<<256, 256>>>();
    xproj_kernel<<<dim3(8, 256), 256>>>(X, Wax, ba, outp);
    rnn_kernel<<<NCTA, 128, RNN_SMEM_BYTES>>>(Waa, outp, hidp);
}